// round 10
// baseline (speedup 1.0000x reference)
#include <cuda_runtime.h>
#include <cuda_bf16.h>
#include <math.h>

// TOF PET forward projection. Grid 128^3, box [-200,200]^3, voxel 3.125mm,
// 128 samples/LOR, TOF sigma=30mm, cutoff 90mm, bin=5.
//
// FOUR LORs per warp (8-lane subgroups); uniform per-LOR setup is SIMD
// across 4 LORs. Per-sample quantities are affine in sample index k; weight
// w = exp2(-u*u), u = fmaf(fk,du,u0), cutoff |u|<=UTHR. Active k-window
// computed analytically (widened +-1). BODY IS BRANCH-FREE: indices are
// always clamped (memory-safe), the cutoff + tail-guard predicate is folded
// into the weight via one select (w=0 outside -- exactly what the reference
// computes). This removes the per-sample BSSY/BSYNC divergence envelope and
// lets the compiler batch the gathers across unrolled iterations (MLP up).
// Tail guard fk<=127 is required (R5 lesson: overshoot lanes past k=127 can
// still be inside the TOF cutoff).

#define GRID_N   128
// TOF_BIN / sqrt(2*pi*TOF_SIGMA2), double-computed, rounded to f32
#define TOF_NORM 0.06649038006690422f
// sC = sqrt(log2(e)/1800); dev^2*log2e/1800 == (dev*sC)^2
#define SC_U     0.028310727f
// 90 * SC_U
#define UTHR     2.5479655f

__global__ __launch_bounds__(256)
void proj_kernel(const float* __restrict__ image,
                 const float* __restrict__ lors,
                 float* __restrict__ out,
                 int n_lors)
{
    const int warp_id = (blockIdx.x * blockDim.x + threadIdx.x) >> 5;
    const int lane    = threadIdx.x & 31;
    const int sub     = lane & 7;            // lane within 8-lane subgroup
    if (warp_id * 4 >= n_lors) return;
    int lor = warp_id * 4 + (lane >> 3);
    const bool live = (lor < n_lors);
    if (!live) lor = 0;                      // dummy work, no store

    // ---- per-LOR setup (uniform across each 8-lane subgroup) ----
    const float* l7 = lors + (size_t)lor * 7;
    const float p1x = l7[0], p1y = l7[1], p1z = l7[2];
    const float dx  = l7[3] - p1x;
    const float dy  = l7[4] - p1y;
    const float dz  = l7[5] - p1z;
    const float tof = l7[6];

    const float L = sqrtf(fmaf(dx, dx, fmaf(dy, dy, dz * dz)));

    // safe_d = where(|d| < 1e-8, 1e-8, d)  (matches reference: +eps)
    const float eps = 1e-8f;
    const float sdx = (fabsf(dx) < eps) ? eps : dx;
    const float sdy = (fabsf(dy) < eps) ? eps : dy;
    const float sdz = (fabsf(dz) < eps) ? eps : dz;

    // slab intersection via fast reciprocals (~2ulp)
    const float rx = __fdividef(1.0f, sdx);
    const float ry = __fdividef(1.0f, sdy);
    const float rz = __fdividef(1.0f, sdz);
    const float tax = (-200.0f - p1x) * rx, tbx = (200.0f - p1x) * rx;
    const float tay = (-200.0f - p1y) * ry, tby = (200.0f - p1y) * ry;
    const float taz = (-200.0f - p1z) * rz, tbz = (200.0f - p1z) * rz;

    float tmin = fmaxf(fmaxf(fminf(tax, tbx), fminf(tay, tby)), fminf(taz, tbz));
    tmin = fmaxf(tmin, 0.0f);
    float tmax = fminf(fminf(fmaxf(tax, tbx), fmaxf(tay, tby)), fmaxf(taz, tbz));
    tmax = fminf(tmax, 1.0f);

    const float valid = (tmax > tmin) ? 1.0f : 0.0f;
    const float span  = fmaxf(tmax - tmin, 0.0f);

    // ---- affine-in-k coefficients ----
    const float cs = span * 0.0078125f;          // dt per sample
    const float t0 = fmaf(0.5f, cs, tmin);       // t at k=0
    const float dL   = cs * L;                   // d(dev)/dk (>= 0)
    const float dev0 = fmaf(t0 - 0.5f, L, -tof); // dev at k=0
    const float du   = dL   * SC_U;              // u slope (>= 0)
    const float u0   = dev0 * SC_U;              // u at k=0
    const float gsx = cs * dx * 0.32f;
    const float gsy = cs * dy * 0.32f;
    const float gsz = cs * dz * 0.32f;
    const float gx0 = (fmaf(t0, dx, p1x) + 200.0f) * 0.32f;
    const float gy0 = (fmaf(t0, dy, p1y) + 200.0f) * 0.32f;
    const float gz0 = (fmaf(t0, dz, p1z) + 200.0f) * 0.32f;

    // ---- active k-window: |dev0 + fk*dL| <= 90, dL >= 0. Widened +-1.
    // Degenerate dL=0 -> rdL=inf: NaN/inf bounds collapse correctly via
    // fmaxf/fminf and F2I saturation.
    const float rdL = __fdividef(1.0f, dL);
    const float klo_f = floorf((-90.0f - dev0) * rdL) - 1.0f;
    const float khi_f = ceilf (( 90.0f - dev0) * rdL) + 1.0f;
    const int klo = (int)fmaxf(klo_f, 0.0f);    // fmaxf(NaN,0)=0
    const int khi = (int)fminf(khi_f, 127.0f);  // fminf(NaN,127)=127

    int niter = ((khi - klo) >> 3) + 1;          // <=0 when window empty
    if (!(tmax > tmin)) niter = 0;               // skip box-missing rays
    float fk = (float)(klo + sub);               // exact small ints
    float acc = 0.0f;

    #pragma unroll 2
    for (; niter > 0; --niter) {
        const float u = fmaf(fk, du, u0);
        // lower clamp via fabs (free modifier; true coords never <= -1, only
        // rounding -eps -> +eps -> floor 0 == clamp); upper via
        // fminf(.,127.99) (128.0 -> 127 == clamp). Always in-bounds.
        const int ix = __float2int_rd(fminf(fabsf(fmaf(fk, gsx, gx0)), 127.99f));
        const int iy = __float2int_rd(fminf(fabsf(fmaf(fk, gsy, gy0)), 127.99f));
        const int iz = __float2int_rd(fminf(fabsf(fmaf(fk, gsz, gz0)), 127.99f));
        const float val = __ldg(&image[ix * 16384 + iy * 128 + iz]);
        float w = exp2f(-u * u);                 // finite u -> clean underflow
        const bool p = (fabsf(u) <= UTHR) && (fk <= 127.0f);
        w = p ? w : 0.0f;                        // FSEL, no branch
        acc = fmaf(val, w, acc);
        fk += 8.0f;
    }

    // ---- 8-lane subgroup reduction ----
    #pragma unroll
    for (int off = 4; off > 0; off >>= 1)
        acc += __shfl_xor_sync(0xFFFFFFFFu, acc, off);

    if (sub == 0 && live) {
        const float step = span * L * (1.0f / 128.0f);
        out[lor] = acc * TOF_NORM * step * valid;
    }
}

extern "C" void kernel_launch(void* const* d_in, const int* in_sizes, int n_in,
                              void* d_out, int out_size)
{
    const float* image = (const float*)d_in[0];
    const float* lors  = (const float*)d_in[1];
    float* out = (float*)d_out;
    const int n_lors = in_sizes[1] / 7;

    const int threads = 256;                       // 8 warps = 32 LORs/block
    const int n_warps = (n_lors + 3) / 4;
    const int blocks  = (n_warps * 32 + threads - 1) / threads;
    proj_kernel<<<blocks, threads>>>(image, lors, out, n_lors);
}

// round 11
// speedup vs baseline: 1.0397x; 1.0397x over previous
#include <cuda_runtime.h>
#include <cuda_bf16.h>
#include <math.h>

// TOF PET forward projection. Grid 128^3, box [-200,200]^3, voxel 3.125mm,
// 128 samples/LOR, TOF sigma=30mm, cutoff 90mm, bin=5.
//
// FOUR LORs per warp (8-lane subgroups); uniform per-LOR setup is SIMD
// across 4 LORs. Per-sample quantities are affine in sample index k; weight
// w = exp2(-u*u), u = fmaf(fk,du,u0), cutoff |u|<=UTHR. Active k-window
// computed analytically (widened +-1); the branchy body skips inactive
// samples (saves L1tex wavefronts -- the near-binding resource).
// Tail-overshoot past k=127 (R5 bug) is prevented STRUCTURALLY: when khi is
// the 127-clamp, klo is aligned down to a multiple of 8 so the last
// iteration is exactly full; when khi is cutoff-derived, overshoot lanes
// fail |u|<=UTHR. So no per-sample tail guard. Voxel clamps reduced to one
// IMNMX on the final address (coords of genuine samples are in [0,128) up
// to rounding; fabs handles -eps, addr-min handles +eps at the top face).

#define GRID_N   128
// TOF_BIN / sqrt(2*pi*TOF_SIGMA2), double-computed, rounded to f32
#define TOF_NORM 0.06649038006690422f
// sC = sqrt(log2(e)/1800); dev^2*log2e/1800 == (dev*sC)^2
#define SC_U     0.028310727f
// 90 * SC_U
#define UTHR     2.5479655f

__global__ __launch_bounds__(256)
void proj_kernel(const float* __restrict__ image,
                 const float* __restrict__ lors,
                 float* __restrict__ out,
                 int n_lors)
{
    const int warp_id = (blockIdx.x * blockDim.x + threadIdx.x) >> 5;
    const int lane    = threadIdx.x & 31;
    const int sub     = lane & 7;            // lane within 8-lane subgroup
    if (warp_id * 4 >= n_lors) return;
    int lor = warp_id * 4 + (lane >> 3);
    const bool live = (lor < n_lors);
    if (!live) lor = 0;                      // dummy work, no store

    // ---- per-LOR setup (uniform across each 8-lane subgroup) ----
    const float* l7 = lors + (size_t)lor * 7;
    const float p1x = l7[0], p1y = l7[1], p1z = l7[2];
    const float dx  = l7[3] - p1x;
    const float dy  = l7[4] - p1y;
    const float dz  = l7[5] - p1z;
    const float tof = l7[6];

    const float L = sqrtf(fmaf(dx, dx, fmaf(dy, dy, dz * dz)));

    // safe_d = where(|d| < 1e-8, 1e-8, d)  (matches reference: +eps)
    const float eps = 1e-8f;
    const float sdx = (fabsf(dx) < eps) ? eps : dx;
    const float sdy = (fabsf(dy) < eps) ? eps : dy;
    const float sdz = (fabsf(dz) < eps) ? eps : dz;

    // slab intersection via fast reciprocals (~2ulp)
    const float rx = __fdividef(1.0f, sdx);
    const float ry = __fdividef(1.0f, sdy);
    const float rz = __fdividef(1.0f, sdz);
    const float tax = (-200.0f - p1x) * rx, tbx = (200.0f - p1x) * rx;
    const float tay = (-200.0f - p1y) * ry, tby = (200.0f - p1y) * ry;
    const float taz = (-200.0f - p1z) * rz, tbz = (200.0f - p1z) * rz;

    float tmin = fmaxf(fmaxf(fminf(tax, tbx), fminf(tay, tby)), fminf(taz, tbz));
    tmin = fmaxf(tmin, 0.0f);
    float tmax = fminf(fminf(fmaxf(tax, tbx), fmaxf(tay, tby)), fmaxf(taz, tbz));
    tmax = fminf(tmax, 1.0f);

    const float valid = (tmax > tmin) ? 1.0f : 0.0f;
    const float span  = fmaxf(tmax - tmin, 0.0f);

    // ---- affine-in-k coefficients ----
    const float cs = span * 0.0078125f;          // dt per sample
    const float t0 = fmaf(0.5f, cs, tmin);       // t at k=0
    const float dL   = cs * L;                   // d(dev)/dk (>= 0)
    const float dev0 = fmaf(t0 - 0.5f, L, -tof); // dev at k=0
    const float du   = dL   * SC_U;              // u slope (>= 0)
    const float u0   = dev0 * SC_U;              // u at k=0
    const float gsx = cs * dx * 0.32f;
    const float gsy = cs * dy * 0.32f;
    const float gsz = cs * dz * 0.32f;
    const float gx0 = (fmaf(t0, dx, p1x) + 200.0f) * 0.32f;
    const float gy0 = (fmaf(t0, dy, p1y) + 200.0f) * 0.32f;
    const float gz0 = (fmaf(t0, dz, p1z) + 200.0f) * 0.32f;

    // ---- active k-window: |dev0 + fk*dL| <= 90, dL >= 0. Widened +-1.
    // Degenerate dL=0 -> rdL=inf: NaN/inf bounds collapse correctly via
    // fmaxf/fminf and F2I saturation.
    const float rdL = __fdividef(1.0f, dL);
    const float klo_f = floorf((-90.0f - dev0) * rdL) - 1.0f;
    const float khi_f = ceilf (( 90.0f - dev0) * rdL) + 1.0f;
    int klo = (int)fmaxf(klo_f, 0.0f);    // fmaxf(NaN,0)=0
    const int khi = (int)fminf(khi_f, 127.0f);  // fminf(NaN,127)=127

    // When khi is the 127-clamp, align klo down so the last iteration is
    // exactly full: no lane can overshoot past k=127 (extra leading samples
    // fail |u|<=UTHR and contribute 0). When khi<127 (cutoff-derived), the
    // +-1 widening margin makes overshoot lanes fail the cutoff.
    if (khi == 127) klo &= ~7;

    int niter = ((khi - klo) >> 3) + 1;          // <=0 when window empty
    if (!(tmax > tmin)) niter = 0;               // skip box-missing rays
    float fk = (float)(klo + sub);               // exact small ints
    float acc = 0.0f;

    #pragma unroll 2
    for (; niter > 0; --niter) {
        const float u = fmaf(fk, du, u0);
        if (fabsf(u) <= UTHR) {
            // genuine samples: coords in [0,128) up to rounding. fabs (free
            // F2I input modifier) maps -eps -> floor 0 == clamp; the single
            // address min handles the ~never +eps case at the top face.
            const int ix = __float2int_rd(fabsf(fmaf(fk, gsx, gx0)));
            const int iy = __float2int_rd(fabsf(fmaf(fk, gsy, gy0)));
            const int iz = __float2int_rd(fabsf(fmaf(fk, gsz, gz0)));
            int addr = ix * 16384 + iy * 128 + iz;
            addr = min(addr, GRID_N * GRID_N * GRID_N - 1);
            const float val = __ldg(&image[addr]);
            const float w = exp2f(-u * u);
            acc = fmaf(val, w, acc);
        }
        fk += 8.0f;
    }

    // ---- 8-lane subgroup reduction ----
    #pragma unroll
    for (int off = 4; off > 0; off >>= 1)
        acc += __shfl_xor_sync(0xFFFFFFFFu, acc, off);

    if (sub == 0 && live) {
        const float step = span * L * (1.0f / 128.0f);
        out[lor] = acc * TOF_NORM * step * valid;
    }
}

extern "C" void kernel_launch(void* const* d_in, const int* in_sizes, int n_in,
                              void* d_out, int out_size)
{
    const float* image = (const float*)d_in[0];
    const float* lors  = (const float*)d_in[1];
    float* out = (float*)d_out;
    const int n_lors = in_sizes[1] / 7;

    const int threads = 256;                       // 8 warps = 32 LORs/block
    const int n_warps = (n_lors + 3) / 4;
    const int blocks  = (n_warps * 32 + threads - 1) / threads;
    proj_kernel<<<blocks, threads>>>(image, lors, out, n_lors);
}

// round 12
// speedup vs baseline: 1.0406x; 1.0009x over previous
#include <cuda_runtime.h>
#include <cuda_bf16.h>
#include <math.h>

// TOF PET forward projection. Grid 128^3, box [-200,200]^3, voxel 3.125mm,
// 128 samples/LOR, TOF sigma=30mm, cutoff 90mm, bin=5.
//
// FOUR LORs per warp (8-lane subgroups); uniform per-LOR setup is SIMD
// across 4 LORs. Per-sample quantities are affine in sample index k; weight
// w = exp2(-u*u), u = fmaf(fk,du,u0), cutoff |u|<=UTHR. Active k-window
// computed analytically (widened +-1); per-sample predicate
// |u|<=UTHR && fk<=127 (tail guard required -- R5 lesson).
//
// KEY CHANGE (R11): the load->consume dependency is SOFTWARE-PIPELINED.
// Previous rounds did val=LDG; acc=FMA(val,..) in the same iteration ->
// MLP=1, one exposed ~240cyc L2 latency per 17-instr iteration (matches the
// measured 65-72% issue ceiling). Now the FMA consumes the PREVIOUS
// iteration's load, loads are PREDICATED (@P LDG: no branch region, and
// predicated-off lanes generate no L1tex wavefronts), and unroll 4 lets
// ptxas batch 4 independent loads in flight.

#define GRID_N   128
// TOF_BIN / sqrt(2*pi*TOF_SIGMA2), double-computed, rounded to f32
#define TOF_NORM 0.06649038006690422f
// sC = sqrt(log2(e)/1800); dev^2*log2e/1800 == (dev*sC)^2
#define SC_U     0.028310727f
// 90 * SC_U
#define UTHR     2.5479655f

__global__ __launch_bounds__(256)
void proj_kernel(const float* __restrict__ image,
                 const float* __restrict__ lors,
                 float* __restrict__ out,
                 int n_lors)
{
    const int warp_id = (blockIdx.x * blockDim.x + threadIdx.x) >> 5;
    const int lane    = threadIdx.x & 31;
    const int sub     = lane & 7;            // lane within 8-lane subgroup
    if (warp_id * 4 >= n_lors) return;
    int lor = warp_id * 4 + (lane >> 3);
    const bool live = (lor < n_lors);
    if (!live) lor = 0;                      // dummy work, no store

    // ---- per-LOR setup (uniform across each 8-lane subgroup) ----
    const float* l7 = lors + (size_t)lor * 7;
    const float p1x = l7[0], p1y = l7[1], p1z = l7[2];
    const float dx  = l7[3] - p1x;
    const float dy  = l7[4] - p1y;
    const float dz  = l7[5] - p1z;
    const float tof = l7[6];

    const float L = sqrtf(fmaf(dx, dx, fmaf(dy, dy, dz * dz)));

    // safe_d = where(|d| < 1e-8, 1e-8, d)  (matches reference: +eps)
    const float eps = 1e-8f;
    const float sdx = (fabsf(dx) < eps) ? eps : dx;
    const float sdy = (fabsf(dy) < eps) ? eps : dy;
    const float sdz = (fabsf(dz) < eps) ? eps : dz;

    // slab intersection via fast reciprocals (~2ulp)
    const float rx = __fdividef(1.0f, sdx);
    const float ry = __fdividef(1.0f, sdy);
    const float rz = __fdividef(1.0f, sdz);
    const float tax = (-200.0f - p1x) * rx, tbx = (200.0f - p1x) * rx;
    const float tay = (-200.0f - p1y) * ry, tby = (200.0f - p1y) * ry;
    const float taz = (-200.0f - p1z) * rz, tbz = (200.0f - p1z) * rz;

    float tmin = fmaxf(fmaxf(fminf(tax, tbx), fminf(tay, tby)), fminf(taz, tbz));
    tmin = fmaxf(tmin, 0.0f);
    float tmax = fminf(fminf(fmaxf(tax, tbx), fmaxf(tay, tby)), fmaxf(taz, tbz));
    tmax = fminf(tmax, 1.0f);

    const float valid = (tmax > tmin) ? 1.0f : 0.0f;
    const float span  = fmaxf(tmax - tmin, 0.0f);

    // ---- affine-in-k coefficients ----
    const float cs = span * 0.0078125f;          // dt per sample
    const float t0 = fmaf(0.5f, cs, tmin);       // t at k=0
    const float dL   = cs * L;                   // d(dev)/dk (>= 0)
    const float dev0 = fmaf(t0 - 0.5f, L, -tof); // dev at k=0
    const float du   = dL   * SC_U;              // u slope (>= 0)
    const float u0   = dev0 * SC_U;              // u at k=0
    const float gsx = cs * dx * 0.32f;
    const float gsy = cs * dy * 0.32f;
    const float gsz = cs * dz * 0.32f;
    const float gx0 = (fmaf(t0, dx, p1x) + 200.0f) * 0.32f;
    const float gy0 = (fmaf(t0, dy, p1y) + 200.0f) * 0.32f;
    const float gz0 = (fmaf(t0, dz, p1z) + 200.0f) * 0.32f;

    // ---- active k-window: |dev0 + fk*dL| <= 90, dL >= 0. Widened +-1.
    // Degenerate dL=0 -> rdL=inf: NaN/inf bounds collapse correctly via
    // fmaxf/fminf and F2I saturation.
    const float rdL = __fdividef(1.0f, dL);
    const float klo_f = floorf((-90.0f - dev0) * rdL) - 1.0f;
    const float khi_f = ceilf (( 90.0f - dev0) * rdL) + 1.0f;
    const int klo = (int)fmaxf(klo_f, 0.0f);    // fmaxf(NaN,0)=0
    const int khi = (int)fminf(khi_f, 127.0f);  // fminf(NaN,127)=127

    int niter = ((khi - klo) >> 3) + 1;          // <=0 when window empty
    if (!(tmax > tmin)) niter = 0;               // skip box-missing rays
    float fk = (float)(klo + sub);               // exact small ints
    float acc = 0.0f;

    // software pipeline registers (previous iteration's load + weight)
    float valp = 0.0f, wp = 0.0f;

    #pragma unroll 4
    for (; niter > 0; --niter) {
        const float u = fmaf(fk, du, u0);
        const bool p = (fabsf(u) <= UTHR) && (fk <= 127.0f);
        // genuine (p-true) samples have coords in [0,128) up to rounding:
        // fabs (free F2I modifier) maps -eps -> 0; one addr min handles the
        // ~never +eps top-face case. p-false lanes never load (predicated),
        // addr clamp keeps even their garbage addresses in-bounds.
        const int ix = __float2int_rd(fabsf(fmaf(fk, gsx, gx0)));
        const int iy = __float2int_rd(fabsf(fmaf(fk, gsy, gy0)));
        const int iz = __float2int_rd(fabsf(fmaf(fk, gsz, gz0)));
        int addr = ix * 16384 + iy * 128 + iz;
        addr = min(addr, GRID_N * GRID_N * GRID_N - 1);
        float val = 0.0f;
        if (p) val = __ldg(&image[addr]);        // @P LDG, no branch region
        const float w = p ? exp2f(-u * u) : 0.0f;
        acc = fmaf(valp, wp, acc);               // consume PREVIOUS load
        valp = val;
        wp   = w;
        fk += 8.0f;
    }
    acc = fmaf(valp, wp, acc);                   // pipeline epilogue

    // ---- 8-lane subgroup reduction ----
    #pragma unroll
    for (int off = 4; off > 0; off >>= 1)
        acc += __shfl_xor_sync(0xFFFFFFFFu, acc, off);

    if (sub == 0 && live) {
        const float step = span * L * (1.0f / 128.0f);
        out[lor] = acc * TOF_NORM * step * valid;
    }
}

extern "C" void kernel_launch(void* const* d_in, const int* in_sizes, int n_in,
                              void* d_out, int out_size)
{
    const float* image = (const float*)d_in[0];
    const float* lors  = (const float*)d_in[1];
    float* out = (float*)d_out;
    const int n_lors = in_sizes[1] / 7;

    const int threads = 256;                       // 8 warps = 32 LORs/block
    const int n_warps = (n_lors + 3) / 4;
    const int blocks  = (n_warps * 32 + threads - 1) / threads;
    proj_kernel<<<blocks, threads>>>(image, lors, out, n_lors);
}